// round 9
// baseline (speedup 1.0000x reference)
#include <cuda_runtime.h>

#define NN   100000
#define NE   1600000
#define NA   1000
#define NB   ((NN + 255) / 256)          // 391 scan blocks
#define FULLMASK 0xffffffffu

// ---------------- scratch (static __device__ globals; no allocs) ----------------
__device__ __align__(16) float g_h1 [NN * 32];   // layer-1 output (all nodes)
__device__ __align__(16) float g_h2 [NN * 32];   // layer-2 output (flagged nodes only)
__device__ float         g_inv[NN];              // 1 / max(indeg, 1)
__device__ int           g_cnt[NN];              // in-degree
__device__ int           g_off[NN];              // CSR row offsets
__device__ int           g_pos[NN];              // placement cursors
__device__ int           g_csr[NE];              // src ids grouped by dst
__device__ int           g_bsum[NB];             // scan block partials
__device__ unsigned char g_need[NN];             // nodes whose h2 feeds the output cone
__device__ int           g_nlist[NN];            // compacted list of flagged nodes
__device__ int           g_nn;                   // #flagged
__device__ int           g_is64;                 // runtime-detected edge dtype

// ---------------- init + dtype detection (merged; detection is warp-parallel) ----
// int32 buffer read as int64 packs two ids/word -> values >= 2^32 >> NN.
__global__ void k_init(const void* ei) {
    int v = blockIdx.x * 256 + threadIdx.x;
    if (v < NN) { g_cnt[v] = 0; g_need[v] = (v < NA) ? 1 : 0; }
    if (v == 0) g_nn = 0;
    if (blockIdx.x == 0 && threadIdx.x < 32) {
        const long long* p = (const long long*)ei;
        unsigned long long w = (unsigned long long)p[threadIdx.x];
        unsigned ok = __ballot_sync(FULLMASK, w < (unsigned long long)NN);
        if (threadIdx.x == 0) g_is64 = (ok == FULLMASK) ? 1 : 0;
    }
}

// ---------------- count degrees + mark layer-3 cone ----------------
__global__ void k_count(const void* ei) {
    int e = blockIdx.x * 256 + threadIdx.x;
    if (e >= NE) return;
    int src, dst;
    if (g_is64) {
        const long long* p = (const long long*)ei;
        src = (int)p[e]; dst = (int)p[NE + e];
    } else {
        const int* p = (const int*)ei;
        src = p[e]; dst = p[NE + e];
    }
    atomicAdd(&g_cnt[dst], 1);
    if (dst < NA) g_need[src] = 1;
}

// ---------------- exclusive scan of g_cnt (shfl-based, 3 kernels) ----------------
__global__ void k_scanA() {
    __shared__ int wsum[8];
    int v    = blockIdx.x * 256 + threadIdx.x;
    int lane = threadIdx.x & 31, w = threadIdx.x >> 5;
    int c = (v < NN) ? g_cnt[v] : 0;
    int s = c;
#pragma unroll
    for (int d = 1; d < 32; d <<= 1) {
        int t = __shfl_up_sync(FULLMASK, s, d);
        if (lane >= d) s += t;
    }
    if (lane == 31) wsum[w] = s;
    __syncthreads();
    if (w == 0 && lane < 8) {
        int t = wsum[lane], u = t;
#pragma unroll
        for (int d = 1; d < 8; d <<= 1) {
            int q = __shfl_up_sync(0xff, u, d);
            if (lane >= d) u += q;
        }
        wsum[lane] = u - t;                      // exclusive warp base
        if (lane == 7) g_bsum[blockIdx.x] = u;   // block total
    }
    __syncthreads();
    if (v < NN) g_off[v] = s - c + wsum[w];      // exclusive within block
}

__global__ void k_scanB() {   // 1 block, 512 threads, NB(=391) <= 512
    __shared__ int wsum[16];
    int t = threadIdx.x, lane = t & 31, w = t >> 5;
    int c = (t < NB) ? g_bsum[t] : 0;
    int s = c;
#pragma unroll
    for (int d = 1; d < 32; d <<= 1) {
        int q = __shfl_up_sync(FULLMASK, s, d);
        if (lane >= d) s += q;
    }
    if (lane == 31) wsum[w] = s;
    __syncthreads();
    if (w == 0 && lane < 16) {
        int a = wsum[lane], u = a;
#pragma unroll
        for (int d = 1; d < 16; d <<= 1) {
            int q = __shfl_up_sync(0xffff, u, d);
            if (lane >= d) u += q;
        }
        wsum[lane] = u - a;
    }
    __syncthreads();
    if (t < NB) g_bsum[t] = s - c + wsum[w];     // exclusive block prefix
}

__global__ void k_scanC() {   // finalize offsets, cursors, inv-degree, flagged list
    int v = blockIdx.x * 256 + threadIdx.x;
    if (v >= NN) return;
    int off = g_off[v] + g_bsum[v >> 8];
    g_off[v] = off;
    g_pos[v] = off;
    int c = g_cnt[v];
    g_inv[v] = 1.0f / (float)(c > 1 ? c : 1);
    if (g_need[v]) { int i = atomicAdd(&g_nn, 1); g_nlist[i] = v; }
}

// ---------------- CSR placement ----------------
__global__ void k_place(const void* ei) {
    int e = blockIdx.x * 256 + threadIdx.x;
    if (e >= NE) return;
    int src, dst;
    if (g_is64) {
        const long long* p = (const long long*)ei;
        src = (int)p[e]; dst = (int)p[NE + e];
    } else {
        const int* p = (const int*)ei;
        src = p[e]; dst = p[NE + e];
    }
    int p_ = atomicAdd(&g_pos[dst], 1);
    g_csr[p_] = src;
}

// ---------------- fused gather + node GEMM ----------------
// Per warp: mean over CSR segment, one feature per lane. 8-wide unroll with
// independent accumulators keeps 8 row-loads in flight (clamped-index
// predication keeps the tail at full MLP too).
__device__ __forceinline__ float gather_mean(const float* __restrict__ X,
                                             int v, int lane) {
    int beg = g_off[v], cnt = g_cnt[v];
    if (cnt == 0) return 0.0f;
    float a0 = 0.f, a1 = 0.f, a2 = 0.f, a3 = 0.f;
    float a4 = 0.f, a5 = 0.f, a6 = 0.f, a7 = 0.f;
    int last = cnt - 1;
    for (int j = 0; j < cnt; j += 8) {
        int e0 = g_csr[beg + min(j + 0, last)];
        int e1 = g_csr[beg + min(j + 1, last)];
        int e2 = g_csr[beg + min(j + 2, last)];
        int e3 = g_csr[beg + min(j + 3, last)];
        int e4 = g_csr[beg + min(j + 4, last)];
        int e5 = g_csr[beg + min(j + 5, last)];
        int e6 = g_csr[beg + min(j + 6, last)];
        int e7 = g_csr[beg + min(j + 7, last)];
        float v0 = X[(size_t)e0 * 32 + lane];
        float v1 = X[(size_t)e1 * 32 + lane];
        float v2 = X[(size_t)e2 * 32 + lane];
        float v3 = X[(size_t)e3 * 32 + lane];
        float v4 = X[(size_t)e4 * 32 + lane];
        float v5 = X[(size_t)e5 * 32 + lane];
        float v6 = X[(size_t)e6 * 32 + lane];
        float v7 = X[(size_t)e7 * 32 + lane];
        a0 += v0;                                  // j+0 < cnt always
        if (j + 1 < cnt) a1 += v1;
        if (j + 2 < cnt) a2 += v2;
        if (j + 3 < cnt) a3 += v3;
        if (j + 4 < cnt) a4 += v4;
        if (j + 5 < cnt) a5 += v5;
        if (j + 6 < cnt) a6 += v6;
        if (j + 7 < cnt) a7 += v7;
    }
    float s = ((a0 + a1) + (a2 + a3)) + ((a4 + a5) + (a6 + a7));
    return s * g_inv[v];
}

__device__ __forceinline__ float node_gemm(float s, float xv,
                                           const float* wl, const float* wr,
                                           float bias) {
    float acc = bias;
#pragma unroll
    for (int k = 0; k < 32; k++) {
        acc = fmaf(__shfl_sync(FULLMASK, s,  k), wl[k], acc);
        acc = fmaf(__shfl_sync(FULLMASK, xv, k), wr[k], acc);
    }
    return fmaxf(acc, 0.0f);
}

// layer 1: all nodes, X = input x, out = g_h1
__global__ void __launch_bounds__(256) k_layer1(const float* __restrict__ X,
                                                const float* __restrict__ Wl,
                                                const float* __restrict__ bl,
                                                const float* __restrict__ Wr) {
    int lane = threadIdx.x & 31;
    int warp = (blockIdx.x * blockDim.x + threadIdx.x) >> 5;
    int nw   = (gridDim.x * blockDim.x) >> 5;
    float wl[32], wr[32];
#pragma unroll
    for (int k = 0; k < 32; k++) { wl[k] = Wl[k * 32 + lane]; wr[k] = Wr[k * 32 + lane]; }
    float bias = bl[lane];
    for (int v = warp; v < NN; v += nw) {
        float s  = gather_mean(X, v, lane);
        float xv = X[(size_t)v * 32 + lane];
        g_h1[(size_t)v * 32 + lane] = node_gemm(s, xv, wl, wr, bias);
    }
}

// layer 2: flagged nodes only, X = g_h1, out = g_h2
__global__ void __launch_bounds__(256) k_layer2(const float* __restrict__ Wl,
                                                const float* __restrict__ bl,
                                                const float* __restrict__ Wr) {
    int lane = threadIdx.x & 31;
    int warp = (blockIdx.x * blockDim.x + threadIdx.x) >> 5;
    int nw   = (gridDim.x * blockDim.x) >> 5;
    float wl[32], wr[32];
#pragma unroll
    for (int k = 0; k < 32; k++) { wl[k] = Wl[k * 32 + lane]; wr[k] = Wr[k * 32 + lane]; }
    float bias = bl[lane];
    int nn = g_nn;
    for (int i = warp; i < nn; i += nw) {
        int v = g_nlist[i];
        float s  = gather_mean(g_h1, v, lane);
        float xv = g_h1[(size_t)v * 32 + lane];
        g_h2[(size_t)v * 32 + lane] = node_gemm(s, xv, wl, wr, bias);
    }
}

// layer 3 + output head: nodes [0, NA), X = g_h2
__global__ void __launch_bounds__(256) k_layer3_out(const float* __restrict__ Wl,
                                                    const float* __restrict__ bl,
                                                    const float* __restrict__ Wr,
                                                    const float* __restrict__ Wo,
                                                    const float* __restrict__ bo,
                                                    float* __restrict__ out) {
    int lane = threadIdx.x & 31;
    int warp = (blockIdx.x * blockDim.x + threadIdx.x) >> 5;
    int nw   = (gridDim.x * blockDim.x) >> 5;
    float wl[32], wr[32], wo[32];
#pragma unroll
    for (int k = 0; k < 32; k++) {
        wl[k] = Wl[k * 32 + lane];
        wr[k] = Wr[k * 32 + lane];
        wo[k] = Wo[k * 8 + (lane & 7)];
    }
    float bias = bl[lane];
    float bob  = bo[lane & 7];
    for (int v = warp; v < NA; v += nw) {
        float s  = gather_mean(g_h2, v, lane);
        float xv = g_h2[(size_t)v * 32 + lane];
        float h  = node_gemm(s, xv, wl, wr, bias);
        float o  = bob;
#pragma unroll
        for (int k = 0; k < 32; k++)
            o = fmaf(__shfl_sync(FULLMASK, h, k), wo[k], o);
        if (lane < 8) out[v * 8 + lane] = o;
    }
}

// ---------------- launch ----------------
extern "C" void kernel_launch(void* const* d_in, const int* in_sizes, int n_in,
                              void* d_out, int out_size) {
    const float* x   = (const float*)d_in[0];
    const void*  ei  = d_in[1];                 // int32 or int64, detected on device
    const float* Wl1 = (const float*)d_in[2];
    const float* bl1 = (const float*)d_in[3];
    const float* Wr1 = (const float*)d_in[4];
    const float* Wl2 = (const float*)d_in[5];
    const float* bl2 = (const float*)d_in[6];
    const float* Wr2 = (const float*)d_in[7];
    const float* Wl3 = (const float*)d_in[8];
    const float* bl3 = (const float*)d_in[9];
    const float* Wr3 = (const float*)d_in[10];
    const float* Wo  = (const float*)d_in[11];
    const float* bo  = (const float*)d_in[12];
    float* out = (float*)d_out;

    const int EB = (NE + 255) / 256;

    k_init  <<<NB, 256>>>(ei);
    k_count <<<EB, 256>>>(ei);
    k_scanA <<<NB, 256>>>();
    k_scanB <<<1, 512>>>();
    k_scanC <<<NB, 256>>>();
    k_place <<<EB, 256>>>(ei);

    k_layer1<<<592, 256>>>(x, Wl1, bl1, Wr1);
    k_layer2<<<592, 256>>>(Wl2, bl2, Wr2);
    k_layer3_out<<<64, 256>>>(Wl3, bl3, Wr3, Wo, bo, out);
}